// round 12
// baseline (speedup 1.0000x reference)
#include <cuda_runtime.h>

// GVCNN group pooling collapsed to out[n,c] = sum_v coef[n,gid[n,v]] * RPs[n,v,c].
//
// One 128-thread block per sample, channel-split across 4 warps: warp w owns
// float2 chunks {32w + lane} (64 channels) of ALL 12 views -> 12-float2
// register tile (24 regs) => launch_bounds(128,9) = 36 warps/SM, raising the
// warps x duty product that has tracked DRAM% all session (R11: 24 warps,
// 70.8%). Per-warp loads: 12 batched coalesced LDG.64 (256B/warp requests).
//
// 27-SHFL transpose-reduce puts this warp's partial y[v] in lane v; ONE
// __syncthreads exchanges the 4 channel-quarter partials; all 4 warps then
// redundantly run the cheap warp-parallel binning (match_any+popc) and
// finish their own channels from their own registers. 1 barrier total.

#define NV 12
#define EPSF 1e-6f

__global__ __launch_bounds__(128, 9) void gvcnn_kernel(
    const float2* __restrict__ RPs2,   // [N, 12, 128] float2
    const float2* __restrict__ w2p,    // [128] float2
    const float*  __restrict__ b,
    float2*       __restrict__ out2)   // [N, 128] float2
{
    const int lane = threadIdx.x & 31;
    const int wid  = threadIdx.x >> 5;           // 0..3
    const size_t n = blockIdx.x;
    const int u    = wid * 32 + lane;            // owned float2 chunk 0..127

    __shared__ float s_y[4][NV];

    // ---- batched loads: 12 independent coalesced LDG.64, nothing between ----
    const float2* base = RPs2 + n * (NV * 128) + u;
    float2 r[NV];
#pragma unroll
    for (int v = 0; v < NV; v++) r[v] = base[v * 128];

    const float2 wv = w2p[u];
    const float  bb = b[0];

    // ---- 12 dot partials over this warp's 64 channels ----
    float p[NV];
#pragma unroll
    for (int v = 0; v < NV; v++)
        p[v] = r[v].x * wv.x + r[v].y * wv.y;

    // ---- transpose-reduce: partial y[v] lands in lane v (27 SHFLs) ----
#pragma unroll
    for (int i = 0; i < NV; i++)
        p[i] += __shfl_xor_sync(0xffffffffu, p[i], 16);

    const bool b8 = (lane & 8) != 0;
    const bool b4 = (lane & 4) != 0;
    const bool b2 = (lane & 2) != 0;
    const bool b1 = (lane & 1) != 0;

    float q8[8];
#pragma unroll
    for (int i = 0; i < 8; i++) {
        const float hiv  = (i + 8 < NV) ? p[i + 8] : 0.f;
        const float send = b8 ? p[i] : hiv;
        const float recv = __shfl_xor_sync(0xffffffffu, send, 8);
        q8[i] = (b8 ? hiv : p[i]) + recv;
    }
    float q4[4];
#pragma unroll
    for (int i = 0; i < 4; i++) {
        const float send = b4 ? q8[i] : q8[i + 4];
        const float recv = __shfl_xor_sync(0xffffffffu, send, 4);
        q4[i] = (b4 ? q8[i + 4] : q8[i]) + recv;
    }
    float q2[2];
#pragma unroll
    for (int i = 0; i < 2; i++) {
        const float send = b2 ? q2[0] * 0.f + (b2 ? q4[i] : q4[i + 2]) : q4[i + 2];
        // (kept simple below)
        (void)send;
        const float snd = b2 ? q4[i] : q4[i + 2];
        const float recv = __shfl_xor_sync(0xffffffffu, snd, 2);
        q2[i] = (b2 ? q4[i + 2] : q4[i]) + recv;
    }
    float yh;
    {
        const float snd = b1 ? q2[0] : q2[1];
        const float recv = __shfl_xor_sync(0xffffffffu, snd, 1);
        yh = (b1 ? q2[1] : q2[0]) + recv;
    }
    // lane v (v<12) holds this warp's channel-quarter partial of y[v].

    if (lane < NV) s_y[wid][lane] = yh;
    __syncthreads();                             // the ONLY barrier

    // ---- warp-parallel binning, redundantly in all 4 warps ----
    const int vl = (lane < NV) ? lane : 0;
    const float y = (s_y[0][vl] + s_y[1][vl]) + (s_y[2][vl] + s_y[3][vl]);

    const float x  = fabsf(y + bb) + EPSF;
    const float s  = x / (1.0f + x);                 // == sigmoid(log(x))
    const int  gid = min((int)(s * 10.0f), 9) >> 1;  // 0..4

    const unsigned mask = __match_any_sync(0xffffffffu, gid) & 0xFFFu;
    const int      gszI = __popc(mask);
    const float    gszF = (float)(gszI | (gszI == 0));
    const float    val  = ceilf(s * gszF);

    float numer = 0.f;
#pragma unroll
    for (int uu = 0; uu < NV; uu++) {
        const float vu = __shfl_sync(0xffffffffu, val, uu);
        if ((mask >> uu) & 1u) numer += vu;
    }
    const float gs = numer / (gszF + EPSF);          // reference group_score

    // total = sum over bins of gs == sum over views of gs/gsize
    float t = (lane < NV) ? gs / gszF : 0.f;
#pragma unroll
    for (int off = 16; off > 0; off >>= 1)
        t += __shfl_xor_sync(0xffffffffu, t, off);

    const float coef = gs / (gszF + EPSF) * (1.0f / (t + EPSF));

    // ---- broadcast the 12 coefficients, then warp-independent epilogue ----
    float cf[NV];
#pragma unroll
    for (int v = 0; v < NV; v++)
        cf[v] = __shfl_sync(0xffffffffu, coef, v);

    float2 acc = make_float2(0.f, 0.f);
#pragma unroll
    for (int v = 0; v < NV; v++) {
        acc.x += cf[v] * r[v].x;
        acc.y += cf[v] * r[v].y;
    }
    out2[n * 128 + u] = acc;
}

extern "C" void kernel_launch(void* const* d_in, const int* in_sizes, int n_in,
                              void* d_out, int out_size)
{
    const float2* RPs2 = (const float2*)d_in[0];   // [8192,12,256] f32
    const float2* w2p  = (const float2*)d_in[1];   // [256] f32
    const float*  b    = (const float*)d_in[2];    // [1] f32
    float2* out2       = (float2*)d_out;           // [8192,256] f32

    const int n = in_sizes[0] / (NV * 256);        // 8192
    gvcnn_kernel<<<n, 128>>>(RPs2, w2p, b, out2);
}

// round 13
// speedup vs baseline: 1.0215x; 1.0215x over previous
#include <cuda_runtime.h>
#include <cstdint>

// GVCNN group pooling collapsed to out[n,c] = sum_v coef[n,gid[n,v]] * RPs[n,v,c].
//
// cp.async (LDGSTS) smem tile breaks the register-tile/occupancy coupling
// that capped R6-R12 at ~70% DRAM: tile lives in smem, regs ~<=64, so
// launch_bounds(64,16) = 16 CTAs = 32 warps/SM at the SAME 6KB-per-warp
// byte coverage as R11 (24 warps, 70.8% DRAM).
//
// Thread t async-copies chunks {v*64+t} (12 batched cp.async.cg, coalesced
// 512B/warp, L1 bypass) and later reads EXACTLY those chunks (channel-split
// compute, chunk u = t), so cp.async.wait_group 0 alone orders the tile --
// no block barrier for the load. Compute = R11 skeleton: 27-SHFL
// transpose-reduce (partial y[v] -> lane v), ONE __syncthreads for the
// 2-warp partial exchange, redundant match_any+popc binning, smem epilogue.

#define NV 12
#define EPSF 1e-6f

__global__ __launch_bounds__(64, 16) void gvcnn_kernel(
    const float4* __restrict__ RPs4,   // [N, 12, 64] float4
    const float4* __restrict__ w4p,    // [64] float4
    const float*  __restrict__ b,
    float4*       __restrict__ out4)   // [N, 64] float4
{
    __shared__ __align__(16) float4 s_tile[NV * 64];   // 12 KB
    __shared__ float s_y[2][NV];

    const int t    = threadIdx.x;                // 0..63, == owned chunk u
    const int lane = t & 31;
    const int half = t >> 5;                     // warp 0 or 1
    const size_t n = blockIdx.x;

    // ---- async tile load: 12 batched 16B copies, L1 bypass ----
    const float4* gsrc = RPs4 + n * (NV * 64) + t;
#pragma unroll
    for (int v = 0; v < NV; v++) {
        const uint32_t dst = (uint32_t)__cvta_generic_to_shared(&s_tile[v * 64 + t]);
        asm volatile("cp.async.cg.shared.global [%0], [%1], 16;"
                     :: "r"(dst), "l"(gsrc + v * 64) : "memory");
    }
    asm volatile("cp.async.commit_group;" ::: "memory");

    const float4 wv = w4p[t];
    const float  bb = b[0];

    asm volatile("cp.async.wait_group 0;" ::: "memory");
    // thread t reads only chunks it copied -> no barrier needed here.

    // ---- 12 dot partials over this warp's 128 channels (from smem) ----
    float p[NV];
#pragma unroll
    for (int v = 0; v < NV; v++) {
        const float4 r = s_tile[v * 64 + t];
        p[v] = r.x * wv.x + r.y * wv.y + r.z * wv.z + r.w * wv.w;
    }

    // ---- transpose-reduce: partial y[v] lands in lane v (27 SHFLs) ----
#pragma unroll
    for (int i = 0; i < NV; i++)
        p[i] += __shfl_xor_sync(0xffffffffu, p[i], 16);

    const bool b8 = (lane & 8) != 0;
    const bool b4 = (lane & 4) != 0;
    const bool b2 = (lane & 2) != 0;
    const bool b1 = (lane & 1) != 0;

    float q8[8];
#pragma unroll
    for (int i = 0; i < 8; i++) {
        const float hiv  = (i + 8 < NV) ? p[i + 8] : 0.f;
        const float send = b8 ? p[i] : hiv;
        const float recv = __shfl_xor_sync(0xffffffffu, send, 8);
        q8[i] = (b8 ? hiv : p[i]) + recv;
    }
    float q4[4];
#pragma unroll
    for (int i = 0; i < 4; i++) {
        const float send = b4 ? q8[i] : q8[i + 4];
        const float recv = __shfl_xor_sync(0xffffffffu, send, 4);
        q4[i] = (b4 ? q8[i + 4] : q8[i]) + recv;
    }
    float q2[2];
#pragma unroll
    for (int i = 0; i < 2; i++) {
        const float send = b2 ? q4[i] : q4[i + 2];
        const float recv = __shfl_xor_sync(0xffffffffu, send, 2);
        q2[i] = (b2 ? q4[i + 2] : q4[i]) + recv;
    }
    float yh;
    {
        const float send = b1 ? q2[0] : q2[1];
        const float recv = __shfl_xor_sync(0xffffffffu, send, 1);
        yh = (b1 ? q2[1] : q2[0]) + recv;
    }
    // lane v (v<12) holds this warp's channel-half partial of y[v].

    if (lane < NV) s_y[half][lane] = yh;
    __syncthreads();                             // the ONLY barrier

    // ---- warp-parallel binning, redundantly in both warps ----
    const int vl = (lane < NV) ? lane : 0;
    const float y = s_y[0][vl] + s_y[1][vl];

    const float x  = fabsf(y + bb) + EPSF;
    const float s  = x / (1.0f + x);                 // == sigmoid(log(x))
    const int  gid = min((int)(s * 10.0f), 9) >> 1;  // 0..4

    const unsigned mask = __match_any_sync(0xffffffffu, gid) & 0xFFFu;
    const int      gszI = __popc(mask);
    const float    gszF = (float)(gszI | (gszI == 0));
    const float    val  = ceilf(s * gszF);

    float numer = 0.f;
#pragma unroll
    for (int uu = 0; uu < NV; uu++) {
        const float vu = __shfl_sync(0xffffffffu, val, uu);
        if ((mask >> uu) & 1u) numer += vu;
    }
    const float gs = numer / (gszF + EPSF);          // reference group_score

    // total = sum over bins of gs == sum over views of gs/gsize
    float tt = (lane < NV) ? gs / gszF : 0.f;
#pragma unroll
    for (int off = 16; off > 0; off >>= 1)
        tt += __shfl_xor_sync(0xffffffffu, tt, off);

    const float coef = gs / (gszF + EPSF) * (1.0f / (tt + EPSF));

    // ---- broadcast 12 coefficients, epilogue from smem ----
    float cf[NV];
#pragma unroll
    for (int v = 0; v < NV; v++)
        cf[v] = __shfl_sync(0xffffffffu, coef, v);

    float4 acc = make_float4(0.f, 0.f, 0.f, 0.f);
#pragma unroll
    for (int v = 0; v < NV; v++) {
        const float4 r = s_tile[v * 64 + t];
        acc.x += cf[v] * r.x;  acc.y += cf[v] * r.y;
        acc.z += cf[v] * r.z;  acc.w += cf[v] * r.w;
    }
    out4[n * 64 + t] = acc;
}

extern "C" void kernel_launch(void* const* d_in, const int* in_sizes, int n_in,
                              void* d_out, int out_size)
{
    const float4* RPs4 = (const float4*)d_in[0];   // [8192,12,256] f32
    const float4* w4p  = (const float4*)d_in[1];   // [256] f32
    const float*  b    = (const float*)d_in[2];    // [1] f32
    float4* out4       = (float4*)d_out;           // [8192,256] f32

    const int n = in_sizes[0] / (NV * 256);        // 8192
    gvcnn_kernel<<<n, 64>>>(RPs4, w4p, b, out4);
}

// round 14
// speedup vs baseline: 1.0359x; 1.0140x over previous
#include <cuda_runtime.h>

// GVCNN group pooling collapsed to out[n,c] = sum_v coef[n,gid[n,v]] * RPs[n,v,c].
//
// R11 skeleton (best: 18.75us, DRAM 70.8% at 24 warps/SM): one 64-thread
// block per sample, channel-split across 2 warps, batched 12xLDG.128
// register tile, 27-SHFL transpose-reduce (partial y[v] -> lane v), ONE
// __syncthreads, redundant warp-parallel binning (match_any+popc),
// warp-independent register epilogue.
//
// R14 change: shave ~11 regs by fusing the coef shfl-broadcast into the
// epilogue FMA loop (no cf[12] array), then __launch_bounds__(64,14):
// 14 CTAs = 28 warps/SM (+17% vs R11) -> higher DRAM duty product.

#define NV 12
#define EPSF 1e-6f

__global__ __launch_bounds__(64, 14) void gvcnn_kernel(
    const float4* __restrict__ RPs4,   // [N, 12, 64] float4
    const float4* __restrict__ w4p,    // [64] float4
    const float*  __restrict__ b,
    float4*       __restrict__ out4)   // [N, 64] float4
{
    const int lane = threadIdx.x & 31;
    const int half = threadIdx.x >> 5;           // warp 0: chunks 0..31, warp 1: 32..63
    const size_t n = blockIdx.x;
    const int u    = half * 32 + lane;           // owned float4 chunk

    __shared__ float s_y[2][NV];

    // ---- batched loads: 12 independent coalesced LDG.128, nothing between ----
    const float4* base = RPs4 + n * (NV * 64) + u;
    float4 r[NV];
#pragma unroll
    for (int v = 0; v < NV; v++) r[v] = base[v * 64];

    const float4 wv = w4p[u];
    const float  bb = b[0];

    // ---- 12 dot partials over this warp's 128 channels ----
    float p[NV];
#pragma unroll
    for (int v = 0; v < NV; v++)
        p[v] = r[v].x * wv.x + r[v].y * wv.y + r[v].z * wv.z + r[v].w * wv.w;

    // ---- transpose-reduce: partial y[v] lands in lane v (27 SHFLs) ----
#pragma unroll
    for (int i = 0; i < NV; i++)
        p[i] += __shfl_xor_sync(0xffffffffu, p[i], 16);

    const bool b8 = (lane & 8) != 0;
    const bool b4 = (lane & 4) != 0;
    const bool b2 = (lane & 2) != 0;
    const bool b1 = (lane & 1) != 0;

    float q8[8];
#pragma unroll
    for (int i = 0; i < 8; i++) {
        const float hiv  = (i + 8 < NV) ? p[i + 8] : 0.f;
        const float send = b8 ? p[i] : hiv;
        const float recv = __shfl_xor_sync(0xffffffffu, send, 8);
        q8[i] = (b8 ? hiv : p[i]) + recv;
    }
    float q4[4];
#pragma unroll
    for (int i = 0; i < 4; i++) {
        const float send = b4 ? q8[i] : q8[i + 4];
        const float recv = __shfl_xor_sync(0xffffffffu, send, 4);
        q4[i] = (b4 ? q8[i + 4] : q8[i]) + recv;
    }
    float q2[2];
#pragma unroll
    for (int i = 0; i < 2; i++) {
        const float send = b2 ? q4[i] : q4[i + 2];
        const float recv = __shfl_xor_sync(0xffffffffu, send, 2);
        q2[i] = (b2 ? q4[i + 2] : q4[i]) + recv;
    }
    float yh;
    {
        const float send = b1 ? q2[0] : q2[1];
        const float recv = __shfl_xor_sync(0xffffffffu, send, 1);
        yh = (b1 ? q2[1] : q2[0]) + recv;
    }
    // lane v (v<12) holds this warp's channel-half partial of y[v].

    if (lane < NV) s_y[half][lane] = yh;
    __syncthreads();                             // the ONLY barrier

    // ---- warp-parallel binning, redundantly in both warps (lane v owns view v) ----
    const int vl = (lane < NV) ? lane : 0;
    const float y = s_y[0][vl] + s_y[1][vl];

    const float x  = fabsf(y + bb) + EPSF;
    const float s  = x / (1.0f + x);                 // == sigmoid(log(x))
    const int  gid = min((int)(s * 10.0f), 9) >> 1;  // 0..4

    const unsigned mask = __match_any_sync(0xffffffffu, gid) & 0xFFFu;
    const int      gszI = __popc(mask);
    const float    gszF = (float)(gszI | (gszI == 0));
    const float    val  = ceilf(s * gszF);

    float numer = 0.f;
#pragma unroll
    for (int uu = 0; uu < NV; uu++) {
        const float vu = __shfl_sync(0xffffffffu, val, uu);
        if ((mask >> uu) & 1u) numer += vu;
    }
    const float gs = numer / (gszF + EPSF);          // reference group_score

    // total = sum over bins of gs == sum over views of gs/gsize
    float t = (lane < NV) ? gs / gszF : 0.f;
#pragma unroll
    for (int off = 16; off > 0; off >>= 1)
        t += __shfl_xor_sync(0xffffffffu, t, off);

    const float coef = gs / (gszF + EPSF) * (1.0f / (t + EPSF));

    // ---- epilogue: fused broadcast+FMA (no cf[] array -> ~11 fewer regs) ----
    float4 acc = make_float4(0.f, 0.f, 0.f, 0.f);
#pragma unroll
    for (int v = 0; v < NV; v++) {
        const float cfv = __shfl_sync(0xffffffffu, coef, v);
        acc.x += cfv * r[v].x;  acc.y += cfv * r[v].y;
        acc.z += cfv * r[v].z;  acc.w += cfv * r[v].w;
    }
    out4[n * 64 + u] = acc;
}

extern "C" void kernel_launch(void* const* d_in, const int* in_sizes, int n_in,
                              void* d_out, int out_size)
{
    const float4* RPs4 = (const float4*)d_in[0];   // [8192,12,256] f32
    const float4* w4p  = (const float4*)d_in[1];   // [256] f32
    const float*  b    = (const float*)d_in[2];    // [1] f32
    float4* out4       = (float4*)d_out;           // [8192,256] f32

    const int n = in_sizes[0] / (NV * 256);        // 8192
    gvcnn_kernel<<<n, 64>>>(RPs4, w4p, b, out4);
}

// round 15
// speedup vs baseline: 1.1235x; 1.0846x over previous
#include <cuda_runtime.h>

// GVCNN group pooling collapsed to out[n,c] = sum_v coef[n,gid[n,v]] * RPs[n,v,c].
//
// Champion R11 skeleton, byte-identical structure (one 64-thread block per
// sample, channel-split across 2 warps, batched 12xLDG.128 register tile,
// 27-SHFL transpose-reduce, ONE __syncthreads, redundant match_any binning,
// warp-independent register epilogue), with two minimal deltas:
//   1) __ldcs / __stcs streaming cache policy: RPs is read-once and out is
//      write-once -- evict-first keeps L2 from thrashing on dead lines.
//   2) launch_bounds(64,13): regs 78 fits 13 CTAs exactly (78*64*13 = 64896),
//      so same codegen, +1 resident CTA = 26 warps/SM.

#define NV 12
#define EPSF 1e-6f

__global__ __launch_bounds__(64, 13) void gvcnn_kernel(
    const float4* __restrict__ RPs4,   // [N, 12, 64] float4
    const float4* __restrict__ w4p,    // [64] float4
    const float*  __restrict__ b,
    float4*       __restrict__ out4)   // [N, 64] float4
{
    const int lane = threadIdx.x & 31;
    const int half = threadIdx.x >> 5;           // warp 0: chunks 0..31, warp 1: 32..63
    const size_t n = blockIdx.x;
    const int u    = half * 32 + lane;           // owned float4 chunk

    __shared__ float s_y[2][NV];

    // ---- batched loads: 12 independent coalesced LDG.128.CS, nothing between ----
    const float4* base = RPs4 + n * (NV * 64) + u;
    float4 r[NV];
#pragma unroll
    for (int v = 0; v < NV; v++) r[v] = __ldcs(base + v * 64);

    const float4 wv = w4p[u];
    const float  bb = b[0];

    // ---- 12 dot partials over this warp's 128 channels ----
    float p[NV];
#pragma unroll
    for (int v = 0; v < NV; v++)
        p[v] = r[v].x * wv.x + r[v].y * wv.y + r[v].z * wv.z + r[v].w * wv.w;

    // ---- transpose-reduce: partial y[v] lands in lane v (27 SHFLs) ----
#pragma unroll
    for (int i = 0; i < NV; i++)
        p[i] += __shfl_xor_sync(0xffffffffu, p[i], 16);

    const bool b8 = (lane & 8) != 0;
    const bool b4 = (lane & 4) != 0;
    const bool b2 = (lane & 2) != 0;
    const bool b1 = (lane & 1) != 0;

    float q8[8];
#pragma unroll
    for (int i = 0; i < 8; i++) {
        const float hiv  = (i + 8 < NV) ? p[i + 8] : 0.f;
        const float send = b8 ? p[i] : hiv;
        const float recv = __shfl_xor_sync(0xffffffffu, send, 8);
        q8[i] = (b8 ? hiv : p[i]) + recv;
    }
    float q4[4];
#pragma unroll
    for (int i = 0; i < 4; i++) {
        const float send = b4 ? q8[i] : q8[i + 4];
        const float recv = __shfl_xor_sync(0xffffffffu, send, 4);
        q4[i] = (b4 ? q8[i + 4] : q8[i]) + recv;
    }
    float q2[2];
#pragma unroll
    for (int i = 0; i < 2; i++) {
        const float send = b2 ? q4[i] : q4[i + 2];
        const float recv = __shfl_xor_sync(0xffffffffu, send, 2);
        q2[i] = (b2 ? q4[i + 2] : q4[i]) + recv;
    }
    float yh;
    {
        const float send = b1 ? q2[0] : q2[1];
        const float recv = __shfl_xor_sync(0xffffffffu, send, 1);
        yh = (b1 ? q2[1] : q2[0]) + recv;
    }
    // lane v (v<12) holds this warp's channel-half partial of y[v].

    if (lane < NV) s_y[half][lane] = yh;
    __syncthreads();                             // the ONLY barrier

    // ---- warp-parallel binning, redundantly in both warps (lane v owns view v) ----
    const int vl = (lane < NV) ? lane : 0;
    const float y = s_y[0][vl] + s_y[1][vl];

    const float x  = fabsf(y + bb) + EPSF;
    const float s  = x / (1.0f + x);                 // == sigmoid(log(x))
    const int  gid = min((int)(s * 10.0f), 9) >> 1;  // 0..4

    const unsigned mask = __match_any_sync(0xffffffffu, gid) & 0xFFFu;
    const int      gszI = __popc(mask);
    const float    gszF = (float)(gszI | (gszI == 0));
    const float    val  = ceilf(s * gszF);

    float numer = 0.f;
#pragma unroll
    for (int uu = 0; uu < NV; uu++) {
        const float vu = __shfl_sync(0xffffffffu, val, uu);
        if ((mask >> uu) & 1u) numer += vu;
    }
    const float gs = numer / (gszF + EPSF);          // reference group_score

    // total = sum over bins of gs == sum over views of gs/gsize
    float t = (lane < NV) ? gs / gszF : 0.f;
#pragma unroll
    for (int off = 16; off > 0; off >>= 1)
        t += __shfl_xor_sync(0xffffffffu, t, off);

    const float coef = gs / (gszF + EPSF) * (1.0f / (t + EPSF));

    // ---- broadcast the 12 coefficients, then warp-independent epilogue ----
    float cf[NV];
#pragma unroll
    for (int v = 0; v < NV; v++)
        cf[v] = __shfl_sync(0xffffffffu, coef, v);

    float4 acc = make_float4(0.f, 0.f, 0.f, 0.f);
#pragma unroll
    for (int v = 0; v < NV; v++) {
        acc.x += cf[v] * r[v].x;  acc.y += cf[v] * r[v].y;
        acc.z += cf[v] * r[v].z;  acc.w += cf[v] * r[v].w;
    }
    __stcs(out4 + n * 64 + u, acc);
}

extern "C" void kernel_launch(void* const* d_in, const int* in_sizes, int n_in,
                              void* d_out, int out_size)
{
    const float4* RPs4 = (const float4*)d_in[0];   // [8192,12,256] f32
    const float4* w4p  = (const float4*)d_in[1];   // [256] f32
    const float*  b    = (const float*)d_in[2];    // [1] f32
    float4* out4       = (float4*)d_out;           // [8192,256] f32

    const int n = in_sizes[0] / (NV * 256);        // 8192
    gvcnn_kernel<<<n, 64>>>(RPs4, w4p, b, out4);
}